// round 14
// baseline (speedup 1.0000x reference)
#include <cuda_runtime.h>
#include <cuda_fp16.h>
#include <math.h>

#define Bz   2048
#define Tz   64
#define HZ   128   // HID
#define FZ   128   // FEAT
#define NB   16    // batch rows per persistent CTA
#define NT   512   // threads per CTA

typedef unsigned long long ull;
typedef unsigned uint32;

// ---------------- scratch (static device globals) ----------------
__device__ unsigned   g_sPT[(size_t)Bz * 4096];   // [b][fq*128+lane*4+e] half2(t0,t1) (32 MB)
__device__ ulonglong2 g_HhP[(size_t)Bz * 1024];   // [b][tp*32+lane] fp16 H packed (32 MB)
__device__ float      g_WhT[HZ * 4 * HZ];         // Whh^T [128h][512j]
__device__ ulonglong2 g_fW[14336];                // fp16 ldsm-tiled weights (224 KB)
//  [0,8192) gates (Whh) | [8192,12288) a_next (W1dc) | [12288,14336) W1h (k_init)
__device__ __half     g_hfc[(size_t)Bz * Tz];     // H[b,t]·fcW  (256 KB)

// ---------------- helpers ----------------
__device__ __forceinline__ float wred(float v) {
#pragma unroll
    for (int o = 16; o > 0; o >>= 1) v += __shfl_xor_sync(0xffffffffu, v, o);
    return v;
}
__device__ __forceinline__ float tanh_approx(float x) {     // MUFU.TANH, ~2^-11
    float r; asm("tanh.approx.f32 %0, %1;" : "=f"(r) : "f"(x)); return r;
}
__device__ __forceinline__ float sigm_t(float x) {          // 1 MUFU sigmoid
    return __fmaf_rn(tanh_approx(0.5f * x), 0.5f, 0.5f);
}
__device__ __forceinline__ __half2 htanh2(__half2 x) {
    unsigned xi = *(unsigned*)&x, r;
    asm("tanh.approx.f16x2 %0, %1;" : "=r"(r) : "r"(xi));
    return *(__half2*)&r;
}
__device__ __forceinline__ ull pack2(float a, float b) {
    return (ull)__float_as_uint(a) | ((ull)__float_as_uint(b) << 32);
}

// ---- tensor-core primitives ----
__device__ __forceinline__ void ldsm4(uint32 &r0, uint32 &r1, uint32 &r2, uint32 &r3, uint32 addr) {
    asm volatile("ldmatrix.sync.aligned.m8n8.x4.shared.b16 {%0,%1,%2,%3}, [%4];"
        : "=r"(r0), "=r"(r1), "=r"(r2), "=r"(r3) : "r"(addr));
}
__device__ __forceinline__ void ldsm4t(uint32 &r0, uint32 &r1, uint32 &r2, uint32 &r3, uint32 addr) {
    asm volatile("ldmatrix.sync.aligned.m8n8.x4.trans.shared.b16 {%0,%1,%2,%3}, [%4];"
        : "=r"(r0), "=r"(r1), "=r"(r2), "=r"(r3) : "r"(addr));
}
__device__ __forceinline__ void mma16816(float4 &d, uint32 a0, uint32 a1, uint32 a2, uint32 a3,
                                         uint32 b0, uint32 b1) {
    asm volatile("mma.sync.aligned.m16n8k16.row.col.f32.f16.f16.f32 "
        "{%0,%1,%2,%3}, {%4,%5,%6,%7}, {%8,%9}, {%0,%1,%2,%3};"
        : "+f"(d.x), "+f"(d.y), "+f"(d.z), "+f"(d.w)
        : "r"(a0), "r"(a1), "r"(a2), "r"(a3), "r"(b0), "r"(b1));
}

// ---------------------------------------------------------------------------
// k_tr: tiled transpose Whh [512,128] -> g_WhT [128,512]
// ---------------------------------------------------------------------------
__global__ void k_tr(const float* __restrict__ Whh) {
    __shared__ float tile[32][33];
    int tx = threadIdx.x, ty = threadIdx.y;
    int x = blockIdx.x * 32 + tx;
    int y = blockIdx.y * 32 + ty;
#pragma unroll
    for (int k = 0; k < 32; k += 8)
        tile[ty + k][tx] = Whh[(y + k) * HZ + x];
    __syncthreads();
    int x2 = blockIdx.y * 32 + tx;
    int y2 = blockIdx.x * 32 + ty;
#pragma unroll
    for (int k = 0; k < 32; k += 8)
        g_WhT[(y2 + k) * 512 + x2] = tile[tx][ty + k];
}

// ---------------------------------------------------------------------------
// k_pack: ldsm-tiled fp16 weights (gates / a_next / W1h-for-init)
// ---------------------------------------------------------------------------
__global__ void k_pack(const float* __restrict__ W1) {
    int idx = blockIdx.x * 256 + threadIdx.x;   // 0..14335
    if (idx >= 14336) return;
    union { ulonglong2 v; __half h[8]; } u;
    if (idx < 8192) {
        int kr = idx & 7, tile = idx >> 3;
        int kt = tile & 15, ng8 = (tile >> 4) & 7, wg = tile >> 7;
        int G = ng8 >> 1, half = ng8 & 1;
        int k = kt * 8 + kr;
        int jb = G * 128 + wg * 16 + half * 8;
#pragma unroll
        for (int nc = 0; nc < 8; ++nc)
            u.h[nc] = __float2half(g_WhT[k * 512 + jb + nc]);
    } else if (idx < 12288) {
        int e = idx - 8192;
        int kr = e & 7, tile = e >> 3;
        int kt = tile & 31, ng = (tile >> 5) & 1, wg = tile >> 6;
        int k = kt * 8 + kr;
        int jb = wg * 16 + ng * 8;
#pragma unroll
        for (int nc = 0; nc < 8; ++nc)
            u.h[nc] = __float2half(__ldg(&W1[k * 128 + jb + nc]));
    } else {
        int e = idx - 12288;
        int kr = e & 7, tile = e >> 3;
        int kt = tile & 15, nt = tile >> 4;
        int k = kt * 8 + kr;
#pragma unroll
        for (int nc = 0; nc < 8; ++nc)
            u.h[nc] = __float2half(__ldg(&W1[(256 + k) * FZ + nt * 8 + nc]));
    }
    g_fW[idx] = u.v;
}

// ---------------------------------------------------------------------------
// k_init (HMMA): sP = H @ W1h + b1 via m16n8k16; also g_HhP + hfc.
// ---------------------------------------------------------------------------
#define KI_SH    0                    // half[64*136]  H fp16        17408
#define KI_SW    17408                // tiled W1h                   32768
#define KI_SOUT  50176                // half[64*136]  sP fp16       17408
#define KI_SB1   67584                // float[128]                    512
#define SMEM_INIT 68096

__global__ void k_init(const float* __restrict__ H,
                       const float* __restrict__ b1,
                       const float* __restrict__ fcW) {
    extern __shared__ char smraw[];
    uint32 smem0 = (uint32)__cvta_generic_to_shared(smraw);
    __half* sH   = (__half*)(smraw + KI_SH);
    __half* sOut = (__half*)(smraw + KI_SOUT);
    float*  sb1  = (float*)(smraw + KI_SB1);
    int b = blockIdx.x, tid = threadIdx.x;
    int w = tid >> 5, lane = tid & 31;

    const float4* Hb4 = (const float4*)(H + (size_t)b * Tz * HZ);
#pragma unroll
    for (int k = 0; k < 8; ++k) {
        int i4 = tid + k * 256;
        int t = i4 >> 5, f = (i4 & 31) * 4;
        float4 v = __ldg(&Hb4[i4]);
        __half2 h0 = __floats2half2_rn(v.x, v.y);
        __half2 h1 = __floats2half2_rn(v.z, v.w);
        *(__half2*)&sH[t * 136 + f]     = h0;
        *(__half2*)&sH[t * 136 + f + 2] = h1;
    }
    for (int i = tid; i < 2048; i += 256)
        ((ulonglong2*)(smraw + KI_SW))[i] = g_fW[12288 + i];
    if (tid < 128) sb1[tid] = __ldg(&b1[tid]);
    __syncthreads();

    {
        int t = tid >> 2, q = tid & 3;
        float acc = 0.0f;
        const __half2* row = (const __half2*)&sH[t * 136 + q * 32];
#pragma unroll
        for (int fp = 0; fp < 16; ++fp) {
            float2 hv = __half22float2(row[fp]);
            int f = q * 32 + 2 * fp;
            acc += hv.x * __ldg(&fcW[f]) + hv.y * __ldg(&fcW[f + 1]);
        }
        acc += __shfl_xor_sync(0xffffffffu, acc, 1, 4);
        acc += __shfl_xor_sync(0xffffffffu, acc, 2, 4);
        if (q == 0) g_hfc[(size_t)b * Tz + t] = __float2half(acc);
    }

    {
        int mt = w & 3, nh = w >> 2;
        int g = lane >> 2, tig = lane & 3;
        int arow = lane & 15;
        int acol = ((lane >> 4) & 1) * 8;
        uint32 A[8][4];
#pragma unroll
        for (int kt = 0; kt < 8; ++kt)
            ldsm4(A[kt][0], A[kt][1], A[kt][2], A[kt][3],
                  smem0 + KI_SH + (mt * 16 + arow) * 272 + (kt * 16 + acol) * 2);
#pragma unroll
        for (int nt2 = 0; nt2 < 8; ++nt2) {
            int nt = nh * 8 + nt2;
            float4 D = make_float4(0.f, 0.f, 0.f, 0.f);
            uint32 tb = smem0 + KI_SW + nt * 2048 + (lane >> 3) * 128 + (lane & 7) * 16;
#pragma unroll
            for (int kq = 0; kq < 4; ++kq) {
                uint32 b0r, b1r, b2r, b3r;
                ldsm4t(b0r, b1r, b2r, b3r, tb + kq * 512);
                mma16816(D, A[2*kq][0],   A[2*kq][1],   A[2*kq][2],   A[2*kq][3],   b0r, b1r);
                mma16816(D, A[2*kq+1][0], A[2*kq+1][1], A[2*kq+1][2], A[2*kq+1][3], b2r, b3r);
            }
            int f0 = nt * 8 + tig * 2;
            int r0 = mt * 16 + g;
            sOut[r0 * 136 + f0]           = __float2half(D.x + sb1[f0]);
            sOut[r0 * 136 + f0 + 1]       = __float2half(D.y + sb1[f0 + 1]);
            sOut[(r0 + 8) * 136 + f0]     = __float2half(D.z + sb1[f0]);
            sOut[(r0 + 8) * 136 + f0 + 1] = __float2half(D.w + sb1[f0 + 1]);
        }
    }
    __syncthreads();

    unsigned* dst = g_sPT + (size_t)b * 4096;
    for (int i = tid; i < 4096; i += 256) {
        int e = i & 3, ln = (i >> 2) & 31, fq = i >> 7;
        int f = 4 * fq + e;
        __half2 hv = __halves2half2(sOut[(2 * ln) * 136 + f], sOut[(2 * ln + 1) * 136 + f]);
        dst[i] = *(unsigned*)&hv;
    }
    ulonglong2* hdst = g_HhP + (size_t)b * 1024;
    for (int i = tid; i < 1024; i += 256) {
        int tp = i >> 5, ln = i & 31;
        ull ux = *(const ull*)&sH[(2 * tp) * 136 + 4 * ln];
        ull uy = *(const ull*)&sH[(2 * tp + 1) * 136 + 4 * ln];
        hdst[i] = make_ulonglong2(ux, uy);
    }
}

// ---------------------------------------------------------------------------
// k_main: per-warp order: [gates MMA] -> [attention (warp-skewed)] -> bar
//         -> [pointwise (1-MUFU sigmoids)] -> bar -> [a_next MMA] -> bar.
// ---------------------------------------------------------------------------
#define SM_WGT   0                 // 192 KB tiled weights
#define SM_SAH   196608            // half[16*128] a                      4096
#define SM_SDH0  200704            // half d buf0 [16 x RB_H]             4352
#define SM_SDH1  205056            // half d buf1                         4352
#define SM_SCH   209408            // half c (a_next A operand)           4352
#define SM_SCF   213760            // float c-state [16 x RB_F]           8448
#define SM_HFC   222208            // half[16*64]                         2048
#define SM_W2    224256            // float[128]                           512
#define SM_WIH   224768            // float[512]                          2048
#define SM_BIA   226816            // float[512]                          2048
#define SM_SY    228864            // float[16]
#define SM_CTXD  228928            // float[16]
#define SMEM_MAIN 228992

#define RB_H 136
#define RB_F 132

__device__ __forceinline__ void attn_row(
    int row, int b, int t, int lane, int fq0, bool do_ctx,
    const __half* sah, const float* sw2, const __half2* shfc2,
    float* sy, float* sctxd,
    const float* __restrict__ Y, float fwy, float fb0,
    const float* __restrict__ fcfW)
{
    const uint4* pT4 = (const uint4*)(g_sPT + (size_t)b * 4096);
    const ull* sar4 = (const ull*)(sah + row * HZ);
    float s0 = 0.0f, s1 = 0.0f;
#pragma unroll 8
    for (int i = 0; i < 32; ++i) {
        int fq = (i + fq0) & 31;                 // warp-skewed start
        uint4 pv = __ldcs(&pT4[fq * 32 + lane]);
        ull av = sar4[fq];
        float4 wf = *(const float4*)&sw2[4 * fq];
        __half ah[4]; *(ull*)ah = av;
        __half2 t0 = htanh2(__hadd2(*(__half2*)&pv.x, __half2half2(ah[0])));
        __half2 t1 = htanh2(__hadd2(*(__half2*)&pv.y, __half2half2(ah[1])));
        __half2 t2 = htanh2(__hadd2(*(__half2*)&pv.z, __half2half2(ah[2])));
        __half2 t3 = htanh2(__hadd2(*(__half2*)&pv.w, __half2half2(ah[3])));
        float2 f0 = __half22float2(t0), f1 = __half22float2(t1);
        float2 f2 = __half22float2(t2), f3 = __half22float2(t3);
        s0 += f0.x * wf.x + f1.x * wf.y + f2.x * wf.z + f3.x * wf.w;
        s1 += f0.y * wf.x + f1.y * wf.y + f2.y * wf.z + f3.y * wf.w;
    }
    float m = fmaxf(s0, s1);
#pragma unroll
    for (int o = 16; o > 0; o >>= 1) m = fmaxf(m, __shfl_xor_sync(0xffffffffu, m, o));
    float e0 = __expf(s0 - m), e1 = __expf(s1 - m);
    float ssum = wred(e0 + e1);
    float inv = __fdividef(1.0f, ssum);
    float beta0 = e0 * inv, beta1 = e1 * inv;

    float2 hc = __half22float2(shfc2[row * 32 + lane]);
    float part = beta0 * hc.x + beta1 * hc.y;
    part = wred(part);
    if (lane == 0)
        sy[row] = part + __ldg(&Y[b * Tz + t]) * fwy + fb0;

    if (do_ctx) {
        const ulonglong2* HbP = g_HhP + (size_t)b * 1024;
        float c0 = 0.f, c1 = 0.f, c2 = 0.f, c3 = 0.f;
#pragma unroll 4
        for (int tp = 0; tp < 32; ++tp) {
            float bbA = __shfl_sync(0xffffffffu, beta0, tp);
            float bbB = __shfl_sync(0xffffffffu, beta1, tp);
            ulonglong2 hv = __ldcs(&HbP[tp * 32 + lane]);
            __half2* hh = (__half2*)&hv;
            float2 a0 = __half22float2(hh[0]), a1 = __half22float2(hh[1]);
            float2 g0 = __half22float2(hh[2]), g1 = __half22float2(hh[3]);
            c0 += bbA * a0.x + bbB * g0.x;
            c1 += bbA * a0.y + bbB * g0.y;
            c2 += bbA * a1.x + bbB * g1.x;
            c3 += bbA * a1.y + bbB * g1.y;
        }
        float4 f2 = *(const float4*)&fcfW[128 + 4 * lane];
        float cd = c0 * f2.x + c1 * f2.y + c2 * f2.z + c3 * f2.w;
        cd = wred(cd);
        if (lane == 0) sctxd[row] = cd;
    }
}

__global__ void __launch_bounds__(NT, 1)
k_main(const float* __restrict__ Y,
       const float* __restrict__ W2,
       const float* __restrict__ W_ih,
       const float* __restrict__ b_ih,
       const float* __restrict__ b_hh,
       const float* __restrict__ fcW,
       const float* __restrict__ fcb,
       const float* __restrict__ fcfW,
       const float* __restrict__ fcfb,
       float* __restrict__ out) {
    extern __shared__ char smraw[];
    uint32 smem0 = (uint32)__cvta_generic_to_shared(smraw);
    __half*  sah   = (__half*)(smraw + SM_SAH);
    __half*  sch   = (__half*)(smraw + SM_SCH);
    float*   scf   = (float*)(smraw + SM_SCF);
    __half2* shfc2 = (__half2*)(smraw + SM_HFC);
    float*   sw2   = (float*)(smraw + SM_W2);
    float*   swih  = (float*)(smraw + SM_WIH);
    float*   sbia  = (float*)(smraw + SM_BIA);
    float*   sy    = (float*)(smraw + SM_SY);
    float*   sctxd = (float*)(smraw + SM_CTXD);

    int tid = threadIdx.x, w = tid >> 5, lane = tid & 31;
    int b0 = blockIdx.x * NB;
    int g = lane >> 2, tig = lane & 3;
    int wg2 = w;

    for (int i = tid; i < 12288; i += NT)
        ((ulonglong2*)smraw)[i] = g_fW[i];
    for (int i = tid; i < NB * HZ; i += NT)
        sah[i] = __float2half(0.0f);
    {
        __half z = __float2half(0.0f);
        __half* sdh0 = (__half*)(smraw + SM_SDH0);
        __half* sdh1 = (__half*)(smraw + SM_SDH1);
        for (int i = tid; i < NB * RB_H; i += NT) { sdh0[i] = z; sdh1[i] = z; sch[i] = z; }
        for (int i = tid; i < NB * RB_F; i += NT) scf[i] = 0.0f;
    }
    for (int i = tid; i < NB * Tz / 2; i += NT)
        shfc2[i] = ((const __half2*)g_hfc)[b0 * 32 + i];
    if (tid < FZ) sw2[tid] = __ldg(&W2[tid]);
    for (int i = tid; i < 512; i += NT) {
        swih[i] = __ldg(&W_ih[i]);
        sbia[i] = __ldg(&b_ih[i]) + __ldg(&b_hh[i]);
    }

    float fwy = __ldg(&fcW[HZ]), fb0 = __ldg(&fcb[0]);
    __syncthreads();

    uint32 gbase[4];
#pragma unroll
    for (int G = 0; G < 4; ++G)
        gbase[G] = smem0 + (((wg2 >> 1) * 8 + G * 2 + (wg2 & 1)) * 2048)
                 + (lane >> 3) * 128 + (lane & 7) * 16;
    uint32 abase = smem0 + 131072 + wg2 * 4096 + (lane >> 3) * 128 + (lane & 7) * 16;
    int jjb = wg2 * 8 + tig * 2;
    int fq0 = (w * 2) & 31;   // per-warp skew

    int arow = (lane & 7) + (lane & 8);
    int acol = ((lane >> 4) & 1) * 8;

    for (int t = 0; t < Tz; ++t) {
        uint32 sdhP = smem0 + ((t & 1) ? SM_SDH1 : SM_SDH0);
        uint32 sdhN = smem0 + ((t & 1) ? SM_SDH0 : SM_SDH1);
        __half* sdhNg = (__half*)(smraw + ((t & 1) ? SM_SDH0 : SM_SDH1));

        // ============ gates MMA FIRST (needs only d(t-1)) =================
        float4 D[4];
        {
            uint32 A[8][4];
#pragma unroll
            for (int kt = 0; kt < 8; ++kt)
                ldsm4(A[kt][0], A[kt][1], A[kt][2], A[kt][3],
                      sdhP + arow * (RB_H * 2) + (kt * 16 + acol) * 2);
#pragma unroll
            for (int G = 0; G < 4; ++G) {
                D[G] = make_float4(0.f, 0.f, 0.f, 0.f);
#pragma unroll
                for (int kq = 0; kq < 4; ++kq) {
                    uint32 b0r, b1r, b2r, b3r;
                    ldsm4t(b0r, b1r, b2r, b3r, gbase[G] + kq * 512);
                    mma16816(D[G], A[2*kq][0],   A[2*kq][1],   A[2*kq][2],   A[2*kq][3],   b0r, b1r);
                    mma16816(D[G], A[2*kq+1][0], A[2*kq+1][1], A[2*kq+1][2], A[2*kq+1][3], b2r, b3r);
                }
            }
        }

        // ============ attention (same warp, D stays in regs) ==============
        attn_row(w, b0 + w, t, lane, fq0, t == Tz - 1,
                 sah, sw2, shfc2, sy, sctxd, Y, fwy, fb0, fcfW);
        __syncthreads();

        // ============ pointwise (1-MUFU sigm/tanh) ========================
        {
            float yt0 = sy[g], yt1 = sy[g + 8];
#pragma unroll
            for (int e = 0; e < 2; ++e) {
                int jj = jjb + e;
                float wi0 = swih[jj],      bi0 = sbia[jj];
                float wi1 = swih[jj+128],  bi1 = sbia[jj+128];
                float wi2 = swih[jj+256],  bi2 = sbia[jj+256];
                float wi3 = swih[jj+384],  bi3 = sbia[jj+384];
#pragma unroll
                for (int rr = 0; rr < 2; ++rr) {
                    int row = g + rr * 8;
                    float yt = rr ? yt1 : yt0;
                    float gi = (e ? (rr ? D[0].w : D[0].y) : (rr ? D[0].z : D[0].x)) + yt * wi0 + bi0;
                    float gf = (e ? (rr ? D[1].w : D[1].y) : (rr ? D[1].z : D[1].x)) + yt * wi1 + bi1;
                    float gg = (e ? (rr ? D[2].w : D[2].y) : (rr ? D[2].z : D[2].x)) + yt * wi2 + bi2;
                    float go = (e ? (rr ? D[3].w : D[3].y) : (rr ? D[3].z : D[3].x)) + yt * wi3 + bi3;
                    float cold = scf[row * RB_F + jj];
                    float cn = sigm_t(gf) * cold + sigm_t(gi) * tanh_approx(gg);
                    float dn = sigm_t(go) * tanh_approx(cn);
                    scf[row * RB_F + jj] = cn;
                    sdhNg[row * RB_H + jj] = __float2half(dn);
                    sch[row * RB_H + jj]   = __float2half(cn);
                }
            }
        }
        __syncthreads();

        // ============ a_next MMA (n8 per warp) ============================
        {
            uint32 schU = smem0 + SM_SCH;
            float4 Da = make_float4(0.f, 0.f, 0.f, 0.f);
#pragma unroll
            for (int kq = 0; kq < 8; ++kq) {
                uint32 b0r, b1r, b2r, b3r;
                ldsm4t(b0r, b1r, b2r, b3r, abase + kq * 512);
                int m0 = 2 * kq, m1 = 2 * kq + 1;
                uint32 a0, a1, a2, a3;
                {
                    uint32 base = (m0 < 8) ? sdhN : schU;
                    int kc = (m0 & 7) * 16;
                    ldsm4(a0, a1, a2, a3, base + arow * (RB_H * 2) + (kc + acol) * 2);
                    mma16816(Da, a0, a1, a2, a3, b0r, b1r);
                }
                {
                    uint32 base = (m1 < 8) ? sdhN : schU;
                    int kc = (m1 & 7) * 16;
                    ldsm4(a0, a1, a2, a3, base + arow * (RB_H * 2) + (kc + acol) * 2);
                    mma16816(Da, a0, a1, a2, a3, b2r, b3r);
                }
            }
            sah[g * HZ + jjb]           = __float2half(Da.x);
            sah[g * HZ + jjb + 1]       = __float2half(Da.y);
            sah[(g + 8) * HZ + jjb]     = __float2half(Da.z);
            sah[(g + 8) * HZ + jjb + 1] = __float2half(Da.w);
        }
        __syncthreads();
    }

    // ---- final: out[b] = d·fcf[0:128] + ctxd + fcfb ----
    {
        const __half* sdh0 = (const __half*)(smraw + SM_SDH0);
        int row = w;
        float4 fa = *(const float4*)&fcfW[4 * lane];
        ull hv = *(const ull*)&sdh0[row * RB_H + 4 * lane];
        __half2* hh = (__half2*)&hv;
        float2 d01 = __half22float2(hh[0]), d23 = __half22float2(hh[1]);
        float s = d01.x * fa.x + d01.y * fa.y + d23.x * fa.z + d23.y * fa.w;
        s = wred(s);
        if (lane == 0) out[b0 + row] = s + sctxd[row] + __ldg(&fcfb[0]);
    }
}

extern "C" void kernel_launch(void* const* d_in, const int* in_sizes, int n_in,
                              void* d_out, int out_size) {
    (void)in_sizes; (void)n_in; (void)out_size;
    const float* H    = (const float*)d_in[0];
    const float* Y    = (const float*)d_in[1];
    const float* W1   = (const float*)d_in[2];
    const float* b1   = (const float*)d_in[3];
    const float* W2   = (const float*)d_in[4];
    // d_in[5] = attn_b2: cancels in softmax.
    const float* W_ih = (const float*)d_in[6];
    const float* Whh  = (const float*)d_in[7];
    const float* b_ih = (const float*)d_in[8];
    const float* b_hh = (const float*)d_in[9];
    const float* fcW  = (const float*)d_in[10];
    const float* fcb  = (const float*)d_in[11];
    const float* fcfW = (const float*)d_in[12];
    const float* fcfb = (const float*)d_in[13];
    float* out = (float*)d_out;

    static int configured = 0;
    if (!configured) {
        cudaFuncSetAttribute(k_init, cudaFuncAttributeMaxDynamicSharedMemorySize, SMEM_INIT);
        cudaFuncSetAttribute(k_main, cudaFuncAttributeMaxDynamicSharedMemorySize, SMEM_MAIN);
        configured = 1;
    }

    k_tr<<<dim3(4, 16), dim3(32, 8)>>>(Whh);
    k_pack<<<56, 256>>>(W1);
    k_init<<<Bz, 256, SMEM_INIT>>>(H, b1, fcW);
    k_main<<<Bz / NB, NT, SMEM_MAIN>>>(Y, W2, W_ih, b_ih, b_hh, fcW, fcb, fcfW, fcfb, out);
}

// round 15
// speedup vs baseline: 1.2242x; 1.2242x over previous
#include <cuda_runtime.h>
#include <cuda_fp16.h>
#include <math.h>

#define Bz   2048
#define Tz   64
#define HZ   128   // HID
#define FZ   128   // FEAT
#define NB   16    // batch rows per persistent CTA
#define NT   512   // threads per CTA

typedef unsigned long long ull;
typedef unsigned uint32;

// ---------------- scratch (static device globals) ----------------
__device__ unsigned   g_sPT[(size_t)Bz * 4096];   // [b][fq*128+lane*4+e] half2(t0,t1) (32 MB)
__device__ ulonglong2 g_HhP[(size_t)Bz * 1024];   // [b][tp*32+lane] fp16 H packed (32 MB)
__device__ float      g_WhT[HZ * 4 * HZ];         // Whh^T [128h][512j]
__device__ ulonglong2 g_fW[14336];                // fp16 ldsm-tiled weights (224 KB)
//  [0,8192) gates (Whh) | [8192,12288) a_next (W1dc) | [12288,14336) W1h (k_init)
__device__ __half     g_hfc[(size_t)Bz * Tz];     // H[b,t]·fcW  (256 KB)

// ---------------- helpers ----------------
__device__ __forceinline__ float wred(float v) {
#pragma unroll
    for (int o = 16; o > 0; o >>= 1) v += __shfl_xor_sync(0xffffffffu, v, o);
    return v;
}
__device__ __forceinline__ float tanh_approx(float x) {
    float r; asm("tanh.approx.f32 %0, %1;" : "=f"(r) : "f"(x)); return r;
}
__device__ __forceinline__ float sigm_t(float x) {          // 1 MUFU sigmoid
    return __fmaf_rn(tanh_approx(0.5f * x), 0.5f, 0.5f);
}
__device__ __forceinline__ __half2 htanh2(__half2 x) {
    unsigned xi = *(unsigned*)&x, r;
    asm("tanh.approx.f16x2 %0, %1;" : "=r"(r) : "r"(xi));
    return *(__half2*)&r;
}
__device__ __forceinline__ ull pack2(float a, float b) {
    return (ull)__float_as_uint(a) | ((ull)__float_as_uint(b) << 32);
}

// ---- tensor-core primitives ----
__device__ __forceinline__ void ldsm4(uint32 &r0, uint32 &r1, uint32 &r2, uint32 &r3, uint32 addr) {
    asm volatile("ldmatrix.sync.aligned.m8n8.x4.shared.b16 {%0,%1,%2,%3}, [%4];"
        : "=r"(r0), "=r"(r1), "=r"(r2), "=r"(r3) : "r"(addr));
}
__device__ __forceinline__ void ldsm4t(uint32 &r0, uint32 &r1, uint32 &r2, uint32 &r3, uint32 addr) {
    asm volatile("ldmatrix.sync.aligned.m8n8.x4.trans.shared.b16 {%0,%1,%2,%3}, [%4];"
        : "=r"(r0), "=r"(r1), "=r"(r2), "=r"(r3) : "r"(addr));
}
__device__ __forceinline__ void mma16816(float4 &d, uint32 a0, uint32 a1, uint32 a2, uint32 a3,
                                         uint32 b0, uint32 b1) {
    asm volatile("mma.sync.aligned.m16n8k16.row.col.f32.f16.f16.f32 "
        "{%0,%1,%2,%3}, {%4,%5,%6,%7}, {%8,%9}, {%0,%1,%2,%3};"
        : "+f"(d.x), "+f"(d.y), "+f"(d.z), "+f"(d.w)
        : "r"(a0), "r"(a1), "r"(a2), "r"(a3), "r"(b0), "r"(b1));
}

// ---------------------------------------------------------------------------
// k_tr: tiled transpose Whh [512,128] -> g_WhT [128,512]
// ---------------------------------------------------------------------------
__global__ void k_tr(const float* __restrict__ Whh) {
    __shared__ float tile[32][33];
    int tx = threadIdx.x, ty = threadIdx.y;
    int x = blockIdx.x * 32 + tx;
    int y = blockIdx.y * 32 + ty;
#pragma unroll
    for (int k = 0; k < 32; k += 8)
        tile[ty + k][tx] = Whh[(y + k) * HZ + x];
    __syncthreads();
    int x2 = blockIdx.y * 32 + tx;
    int y2 = blockIdx.x * 32 + ty;
#pragma unroll
    for (int k = 0; k < 32; k += 8)
        g_WhT[(y2 + k) * 512 + x2] = tile[tx][ty + k];
}

// ---------------------------------------------------------------------------
// k_pack: ldsm-tiled fp16 weights (gates / a_next / W1h-for-init)
// ---------------------------------------------------------------------------
__global__ void k_pack(const float* __restrict__ W1) {
    int idx = blockIdx.x * 256 + threadIdx.x;   // 0..14335
    if (idx >= 14336) return;
    union { ulonglong2 v; __half h[8]; } u;
    if (idx < 8192) {
        int kr = idx & 7, tile = idx >> 3;
        int kt = tile & 15, ng8 = (tile >> 4) & 7, wg = tile >> 7;
        int G = ng8 >> 1, half = ng8 & 1;
        int k = kt * 8 + kr;
        int jb = G * 128 + wg * 16 + half * 8;
#pragma unroll
        for (int nc = 0; nc < 8; ++nc)
            u.h[nc] = __float2half(g_WhT[k * 512 + jb + nc]);
    } else if (idx < 12288) {
        int e = idx - 8192;
        int kr = e & 7, tile = e >> 3;
        int kt = tile & 31, ng = (tile >> 5) & 1, wg = tile >> 6;
        int k = kt * 8 + kr;
        int jb = wg * 16 + ng * 8;
#pragma unroll
        for (int nc = 0; nc < 8; ++nc)
            u.h[nc] = __float2half(__ldg(&W1[k * 128 + jb + nc]));
    } else {
        int e = idx - 12288;
        int kr = e & 7, tile = e >> 3;
        int kt = tile & 15, nt = tile >> 4;
        int k = kt * 8 + kr;
#pragma unroll
        for (int nc = 0; nc < 8; ++nc)
            u.h[nc] = __float2half(__ldg(&W1[(256 + k) * FZ + nt * 8 + nc]));
    }
    g_fW[idx] = u.v;
}

// ---------------------------------------------------------------------------
// k_init (HMMA): sP = H @ W1h + b1 via m16n8k16; also g_HhP + hfc.
// ---------------------------------------------------------------------------
#define KI_SH    0                    // half[64*136]  H fp16        17408
#define KI_SW    17408                // tiled W1h                   32768
#define KI_SOUT  50176                // half[64*136]  sP fp16       17408
#define KI_SB1   67584                // float[128]                    512
#define SMEM_INIT 68096

__global__ void k_init(const float* __restrict__ H,
                       const float* __restrict__ b1,
                       const float* __restrict__ fcW) {
    extern __shared__ char smraw[];
    uint32 smem0 = (uint32)__cvta_generic_to_shared(smraw);
    __half* sH   = (__half*)(smraw + KI_SH);
    __half* sOut = (__half*)(smraw + KI_SOUT);
    float*  sb1  = (float*)(smraw + KI_SB1);
    int b = blockIdx.x, tid = threadIdx.x;
    int w = tid >> 5, lane = tid & 31;

    const float4* Hb4 = (const float4*)(H + (size_t)b * Tz * HZ);
#pragma unroll
    for (int k = 0; k < 8; ++k) {
        int i4 = tid + k * 256;
        int t = i4 >> 5, f = (i4 & 31) * 4;
        float4 v = __ldg(&Hb4[i4]);
        __half2 h0 = __floats2half2_rn(v.x, v.y);
        __half2 h1 = __floats2half2_rn(v.z, v.w);
        *(__half2*)&sH[t * 136 + f]     = h0;
        *(__half2*)&sH[t * 136 + f + 2] = h1;
    }
    for (int i = tid; i < 2048; i += 256)
        ((ulonglong2*)(smraw + KI_SW))[i] = g_fW[12288 + i];
    if (tid < 128) sb1[tid] = __ldg(&b1[tid]);
    __syncthreads();

    {
        int t = tid >> 2, q = tid & 3;
        float acc = 0.0f;
        const __half2* row = (const __half2*)&sH[t * 136 + q * 32];
#pragma unroll
        for (int fp = 0; fp < 16; ++fp) {
            float2 hv = __half22float2(row[fp]);
            int f = q * 32 + 2 * fp;
            acc += hv.x * __ldg(&fcW[f]) + hv.y * __ldg(&fcW[f + 1]);
        }
        acc += __shfl_xor_sync(0xffffffffu, acc, 1, 4);
        acc += __shfl_xor_sync(0xffffffffu, acc, 2, 4);
        if (q == 0) g_hfc[(size_t)b * Tz + t] = __float2half(acc);
    }

    {
        int mt = w & 3, nh = w >> 2;
        int g = lane >> 2, tig = lane & 3;
        int arow = lane & 15;
        int acol = ((lane >> 4) & 1) * 8;
        uint32 A[8][4];
#pragma unroll
        for (int kt = 0; kt < 8; ++kt)
            ldsm4(A[kt][0], A[kt][1], A[kt][2], A[kt][3],
                  smem0 + KI_SH + (mt * 16 + arow) * 272 + (kt * 16 + acol) * 2);
#pragma unroll
        for (int nt2 = 0; nt2 < 8; ++nt2) {
            int nt = nh * 8 + nt2;
            float4 D = make_float4(0.f, 0.f, 0.f, 0.f);
            uint32 tb = smem0 + KI_SW + nt * 2048 + (lane >> 3) * 128 + (lane & 7) * 16;
#pragma unroll
            for (int kq = 0; kq < 4; ++kq) {
                uint32 b0r, b1r, b2r, b3r;
                ldsm4t(b0r, b1r, b2r, b3r, tb + kq * 512);
                mma16816(D, A[2*kq][0],   A[2*kq][1],   A[2*kq][2],   A[2*kq][3],   b0r, b1r);
                mma16816(D, A[2*kq+1][0], A[2*kq+1][1], A[2*kq+1][2], A[2*kq+1][3], b2r, b3r);
            }
            int f0 = nt * 8 + tig * 2;
            int r0 = mt * 16 + g;
            sOut[r0 * 136 + f0]           = __float2half(D.x + sb1[f0]);
            sOut[r0 * 136 + f0 + 1]       = __float2half(D.y + sb1[f0 + 1]);
            sOut[(r0 + 8) * 136 + f0]     = __float2half(D.z + sb1[f0]);
            sOut[(r0 + 8) * 136 + f0 + 1] = __float2half(D.w + sb1[f0 + 1]);
        }
    }
    __syncthreads();

    unsigned* dst = g_sPT + (size_t)b * 4096;
    for (int i = tid; i < 4096; i += 256) {
        int e = i & 3, ln = (i >> 2) & 31, fq = i >> 7;
        int f = 4 * fq + e;
        __half2 hv = __halves2half2(sOut[(2 * ln) * 136 + f], sOut[(2 * ln + 1) * 136 + f]);
        dst[i] = *(unsigned*)&hv;
    }
    ulonglong2* hdst = g_HhP + (size_t)b * 1024;
    for (int i = tid; i < 1024; i += 256) {
        int tp = i >> 5, ln = i & 31;
        ull ux = *(const ull*)&sH[(2 * tp) * 136 + 4 * ln];
        ull uy = *(const ull*)&sH[(2 * tp + 1) * 136 + 4 * ln];
        hdst[i] = make_ulonglong2(ux, uy);
    }
}

// ---------------------------------------------------------------------------
// k_main: gates weights in REGISTER fragments (smem ~98 KB -> L1D ~130 KB).
// Per-warp order: [gates MMA (reg frags)] -> [attention] -> bar
//                 -> [pointwise] -> bar -> [a_next MMA (smem)] -> bar.
// ---------------------------------------------------------------------------
#define SM_ANX   0                 // a_next tiles (also staging)        65536
#define SM_SAH   65536             // half[16*128] a                      4096
#define SM_SDH0  69632             // half d buf0 [16 x RB_H]             4352
#define SM_SDH1  73984             // half d buf1                         4352
#define SM_SCH   78336             // half c (a_next A operand)           4352
#define SM_SCF   82688             // float c-state [16 x RB_F]           8448
#define SM_HFC   91136             // half[16*64]                         2048
#define SM_W2    93184             // float[128]                           512
#define SM_WIH   93696             // float[512]                          2048
#define SM_BIA   95744             // float[512]                          2048
#define SM_SY    97792             // float[16]
#define SM_CTXD  97856             // float[16]
#define SMEM_MAIN 97920

#define RB_H 136
#define RB_F 132

__device__ __forceinline__ void attn_row(
    int row, int b, int t, int lane, bool do_ctx,
    const __half* sah, const float* sw2, const __half2* shfc2,
    float* sy, float* sctxd,
    const float* __restrict__ Y, float fwy, float fb0,
    const float* __restrict__ fcfW)
{
    const uint4* pT4 = (const uint4*)(g_sPT + (size_t)b * 4096);
    const ull* sar4 = (const ull*)(sah + row * HZ);
    float s0 = 0.0f, s1 = 0.0f;
#pragma unroll 8
    for (int fq = 0; fq < 32; ++fq) {
        uint4 pv = pT4[fq * 32 + lane];          // default caching: let L1 keep it
        ull av = sar4[fq];
        float4 wf = *(const float4*)&sw2[4 * fq];
        __half ah[4]; *(ull*)ah = av;
        __half2 t0 = htanh2(__hadd2(*(__half2*)&pv.x, __half2half2(ah[0])));
        __half2 t1 = htanh2(__hadd2(*(__half2*)&pv.y, __half2half2(ah[1])));
        __half2 t2 = htanh2(__hadd2(*(__half2*)&pv.z, __half2half2(ah[2])));
        __half2 t3 = htanh2(__hadd2(*(__half2*)&pv.w, __half2half2(ah[3])));
        float2 f0 = __half22float2(t0), f1 = __half22float2(t1);
        float2 f2 = __half22float2(t2), f3 = __half22float2(t3);
        s0 += f0.x * wf.x + f1.x * wf.y + f2.x * wf.z + f3.x * wf.w;
        s1 += f0.y * wf.x + f1.y * wf.y + f2.y * wf.z + f3.y * wf.w;
    }
    float m = fmaxf(s0, s1);
#pragma unroll
    for (int o = 16; o > 0; o >>= 1) m = fmaxf(m, __shfl_xor_sync(0xffffffffu, m, o));
    float e0 = __expf(s0 - m), e1 = __expf(s1 - m);
    float ssum = wred(e0 + e1);
    float inv = __fdividef(1.0f, ssum);
    float beta0 = e0 * inv, beta1 = e1 * inv;

    float2 hc = __half22float2(shfc2[row * 32 + lane]);
    float part = beta0 * hc.x + beta1 * hc.y;
    part = wred(part);
    if (lane == 0)
        sy[row] = part + __ldg(&Y[b * Tz + t]) * fwy + fb0;

    if (do_ctx) {
        const ulonglong2* HbP = g_HhP + (size_t)b * 1024;
        float c0 = 0.f, c1 = 0.f, c2 = 0.f, c3 = 0.f;
#pragma unroll 4
        for (int tp = 0; tp < 32; ++tp) {
            float bbA = __shfl_sync(0xffffffffu, beta0, tp);
            float bbB = __shfl_sync(0xffffffffu, beta1, tp);
            ulonglong2 hv = __ldcs(&HbP[tp * 32 + lane]);
            __half2* hh = (__half2*)&hv;
            float2 a0 = __half22float2(hh[0]), a1 = __half22float2(hh[1]);
            float2 g0 = __half22float2(hh[2]), g1 = __half22float2(hh[3]);
            c0 += bbA * a0.x + bbB * g0.x;
            c1 += bbA * a0.y + bbB * g0.y;
            c2 += bbA * a1.x + bbB * g1.x;
            c3 += bbA * a1.y + bbB * g1.y;
        }
        float4 f2 = *(const float4*)&fcfW[128 + 4 * lane];
        float cd = c0 * f2.x + c1 * f2.y + c2 * f2.z + c3 * f2.w;
        cd = wred(cd);
        if (lane == 0) sctxd[row] = cd;
    }
}

__global__ void __launch_bounds__(NT, 1)
k_main(const float* __restrict__ Y,
       const float* __restrict__ W2,
       const float* __restrict__ W_ih,
       const float* __restrict__ b_ih,
       const float* __restrict__ b_hh,
       const float* __restrict__ fcW,
       const float* __restrict__ fcb,
       const float* __restrict__ fcfW,
       const float* __restrict__ fcfb,
       float* __restrict__ out) {
    extern __shared__ char smraw[];
    uint32 smem0 = (uint32)__cvta_generic_to_shared(smraw);
    __half*  sah   = (__half*)(smraw + SM_SAH);
    __half*  sch   = (__half*)(smraw + SM_SCH);
    float*   scf   = (float*)(smraw + SM_SCF);
    __half2* shfc2 = (__half2*)(smraw + SM_HFC);
    float*   sw2   = (float*)(smraw + SM_W2);
    float*   swih  = (float*)(smraw + SM_WIH);
    float*   sbia  = (float*)(smraw + SM_BIA);
    float*   sy    = (float*)(smraw + SM_SY);
    float*   sctxd = (float*)(smraw + SM_CTXD);

    int tid = threadIdx.x, w = tid >> 5, lane = tid & 31;
    int b0 = blockIdx.x * NB;
    int g = lane >> 2, tig = lane & 3;
    int wg2 = w;

    // ---- stage gates weights -> register fragments (2 chunks of 64 KB) ----
    uint32 BG[64];   // [G][kq][4]
    {
        int lanehi = (lane >> 3) * 128 + (lane & 7) * 16;
        // chunk 0: tile-groups 0..31 (warps 0-7)
        for (int i = tid; i < 4096; i += NT)
            ((ulonglong2*)smraw)[i] = g_fW[i];
        __syncthreads();
        if (wg2 < 8) {
#pragma unroll
            for (int G = 0; G < 4; ++G) {
                int grp = (wg2 >> 1) * 8 + G * 2 + (wg2 & 1);
                uint32 tb = smem0 + grp * 2048 + lanehi;
#pragma unroll
                for (int kq = 0; kq < 4; ++kq)
                    ldsm4t(BG[G*16 + kq*4 + 0], BG[G*16 + kq*4 + 1],
                           BG[G*16 + kq*4 + 2], BG[G*16 + kq*4 + 3], tb + kq * 512);
            }
        }
        __syncthreads();
        // chunk 1: tile-groups 32..63 (warps 8-15)
        for (int i = tid; i < 4096; i += NT)
            ((ulonglong2*)smraw)[i] = g_fW[4096 + i];
        __syncthreads();
        if (wg2 >= 8) {
#pragma unroll
            for (int G = 0; G < 4; ++G) {
                int grp = (wg2 >> 1) * 8 + G * 2 + (wg2 & 1) - 32;
                uint32 tb = smem0 + grp * 2048 + lanehi;
#pragma unroll
                for (int kq = 0; kq < 4; ++kq)
                    ldsm4t(BG[G*16 + kq*4 + 0], BG[G*16 + kq*4 + 1],
                           BG[G*16 + kq*4 + 2], BG[G*16 + kq*4 + 3], tb + kq * 512);
            }
        }
        __syncthreads();
        // now load a_next tiles into SM_ANX permanently
        for (int i = tid; i < 4096; i += NT)
            ((ulonglong2*)smraw)[i] = g_fW[8192 + i];
    }

    for (int i = tid; i < NB * HZ; i += NT)
        sah[i] = __float2half(0.0f);
    {
        __half z = __float2half(0.0f);
        __half* sdh0 = (__half*)(smraw + SM_SDH0);
        __half* sdh1 = (__half*)(smraw + SM_SDH1);
        for (int i = tid; i < NB * RB_H; i += NT) { sdh0[i] = z; sdh1[i] = z; sch[i] = z; }
        for (int i = tid; i < NB * RB_F; i += NT) scf[i] = 0.0f;
    }
    for (int i = tid; i < NB * Tz / 2; i += NT)
        shfc2[i] = ((const __half2*)g_hfc)[b0 * 32 + i];
    if (tid < FZ) sw2[tid] = __ldg(&W2[tid]);
    for (int i = tid; i < 512; i += NT) {
        swih[i] = __ldg(&W_ih[i]);
        sbia[i] = __ldg(&b_ih[i]) + __ldg(&b_hh[i]);
    }

    float fwy = __ldg(&fcW[HZ]), fb0 = __ldg(&fcb[0]);
    __syncthreads();

    uint32 abase = smem0 + SM_ANX + wg2 * 4096 + (lane >> 3) * 128 + (lane & 7) * 16;
    int jjb = wg2 * 8 + tig * 2;
    int arow = (lane & 7) + (lane & 8);
    int acol = ((lane >> 4) & 1) * 8;

    for (int t = 0; t < Tz; ++t) {
        uint32 sdhP = smem0 + ((t & 1) ? SM_SDH1 : SM_SDH0);
        uint32 sdhN = smem0 + ((t & 1) ? SM_SDH0 : SM_SDH1);
        __half* sdhNg = (__half*)(smraw + ((t & 1) ? SM_SDH0 : SM_SDH1));

        // ============ gates MMA FIRST (register B-frags) ==================
        float4 D[4];
        {
            uint32 A[8][4];
#pragma unroll
            for (int kt = 0; kt < 8; ++kt)
                ldsm4(A[kt][0], A[kt][1], A[kt][2], A[kt][3],
                      sdhP + arow * (RB_H * 2) + (kt * 16 + acol) * 2);
#pragma unroll
            for (int G = 0; G < 4; ++G) {
                D[G] = make_float4(0.f, 0.f, 0.f, 0.f);
#pragma unroll
                for (int kq = 0; kq < 4; ++kq) {
                    mma16816(D[G], A[2*kq][0],   A[2*kq][1],   A[2*kq][2],   A[2*kq][3],
                             BG[G*16 + kq*4 + 0], BG[G*16 + kq*4 + 1]);
                    mma16816(D[G], A[2*kq+1][0], A[2*kq+1][1], A[2*kq+1][2], A[2*kq+1][3],
                             BG[G*16 + kq*4 + 2], BG[G*16 + kq*4 + 3]);
                }
            }
        }

        // ============ attention (same warp, D stays in regs) ==============
        attn_row(w, b0 + w, t, lane, t == Tz - 1,
                 sah, sw2, shfc2, sy, sctxd, Y, fwy, fb0, fcfW);
        __syncthreads();

        // ============ pointwise (1-MUFU sigm/tanh) ========================
        {
            float yt0 = sy[g], yt1 = sy[g + 8];
#pragma unroll
            for (int e = 0; e < 2; ++e) {
                int jj = jjb + e;
                float wi0 = swih[jj],      bi0 = sbia[jj];
                float wi1 = swih[jj+128],  bi1 = sbia[jj+128];
                float wi2 = swih[jj+256],  bi2 = sbia[jj+256];
                float wi3 = swih[jj+384],  bi3 = sbia[jj+384];
#pragma unroll
                for (int rr = 0; rr < 2; ++rr) {
                    int row = g + rr * 8;
                    float yt = rr ? yt1 : yt0;
                    float gi = (e ? (rr ? D[0].w : D[0].y) : (rr ? D[0].z : D[0].x)) + yt * wi0 + bi0;
                    float gf = (e ? (rr ? D[1].w : D[1].y) : (rr ? D[1].z : D[1].x)) + yt * wi1 + bi1;
                    float gg = (e ? (rr ? D[2].w : D[2].y) : (rr ? D[2].z : D[2].x)) + yt * wi2 + bi2;
                    float go = (e ? (rr ? D[3].w : D[3].y) : (rr ? D[3].z : D[3].x)) + yt * wi3 + bi3;
                    float cold = scf[row * RB_F + jj];
                    float cn = sigm_t(gf) * cold + sigm_t(gi) * tanh_approx(gg);
                    float dn = sigm_t(go) * tanh_approx(cn);
                    scf[row * RB_F + jj] = cn;
                    sdhNg[row * RB_H + jj] = __float2half(dn);
                    sch[row * RB_H + jj]   = __float2half(cn);
                }
            }
        }
        __syncthreads();

        // ============ a_next MMA (n8 per warp, weights in smem) ===========
        {
            uint32 schU = smem0 + SM_SCH;
            float4 Da = make_float4(0.f, 0.f, 0.f, 0.f);
#pragma unroll
            for (int kq = 0; kq < 8; ++kq) {
                uint32 b0r, b1r, b2r, b3r;
                ldsm4t(b0r, b1r, b2r, b3r, abase + kq * 512);
                int m0 = 2 * kq, m1 = 2 * kq + 1;
                uint32 a0, a1, a2, a3;
                {
                    uint32 base = (m0 < 8) ? sdhN : schU;
                    int kc = (m0 & 7) * 16;
                    ldsm4(a0, a1, a2, a3, base + arow * (RB_H * 2) + (kc + acol) * 2);
                    mma16816(Da, a0, a1, a2, a3, b0r, b1r);
                }
                {
                    uint32 base = (m1 < 8) ? sdhN : schU;
                    int kc = (m1 & 7) * 16;
                    ldsm4(a0, a1, a2, a3, base + arow * (RB_H * 2) + (kc + acol) * 2);
                    mma16816(Da, a0, a1, a2, a3, b2r, b3r);
                }
            }
            sah[g * HZ + jjb]           = __float2half(Da.x);
            sah[g * HZ + jjb + 1]       = __float2half(Da.y);
            sah[(g + 8) * HZ + jjb]     = __float2half(Da.z);
            sah[(g + 8) * HZ + jjb + 1] = __float2half(Da.w);
        }
        __syncthreads();
    }

    // ---- final: out[b] = d·fcf[0:128] + ctxd + fcfb ----
    {
        const __half* sdh0 = (const __half*)(smraw + SM_SDH0);
        int row = w;
        float4 fa = *(const float4*)&fcfW[4 * lane];
        ull hv = *(const ull*)&sdh0[row * RB_H + 4 * lane];
        __half2* hh = (__half2*)&hv;
        float2 d01 = __half22float2(hh[0]), d23 = __half22float2(hh[1]);
        float s = d01.x * fa.x + d01.y * fa.y + d23.x * fa.z + d23.y * fa.w;
        s = wred(s);
        if (lane == 0) out[b0 + row] = s + sctxd[row] + __ldg(&fcfb[0]);
    }
}

extern "C" void kernel_launch(void* const* d_in, const int* in_sizes, int n_in,
                              void* d_out, int out_size) {
    (void)in_sizes; (void)n_in; (void)out_size;
    const float* H    = (const float*)d_in[0];
    const float* Y    = (const float*)d_in[1];
    const float* W1   = (const float*)d_in[2];
    const float* b1   = (const float*)d_in[3];
    const float* W2   = (const float*)d_in[4];
    // d_in[5] = attn_b2: cancels in softmax.
    const float* W_ih = (const float*)d_in[6];
    const float* Whh  = (const float*)d_in[7];
    const float* b_ih = (const float*)d_in[8];
    const float* b_hh = (const float*)d_in[9];
    const float* fcW  = (const float*)d_in[10];
    const float* fcb  = (const float*)d_in[11];
    const float* fcfW = (const float*)d_in[12];
    const float* fcfb = (const float*)d_in[13];
    float* out = (float*)d_out;

    static int configured = 0;
    if (!configured) {
        cudaFuncSetAttribute(k_init, cudaFuncAttributeMaxDynamicSharedMemorySize, SMEM_INIT);
        cudaFuncSetAttribute(k_main, cudaFuncAttributeMaxDynamicSharedMemorySize, SMEM_MAIN);
        configured = 1;
    }

    k_tr<<<dim3(4, 16), dim3(32, 8)>>>(Whh);
    k_pack<<<56, 256>>>(W1);
    k_init<<<Bz, 256, SMEM_INIT>>>(H, b1, fcW);
    k_main<<<Bz / NB, NT, SMEM_MAIN>>>(Y, W2, W_ih, b_ih, b_hh, fcW, fcb, fcfW, fcfb, out);
}

// round 16
// speedup vs baseline: 1.2369x; 1.0104x over previous
#include <cuda_runtime.h>
#include <cuda_fp16.h>
#include <math.h>

#define Bz   2048
#define Tz   64
#define HZ   128   // HID
#define FZ   128   // FEAT
#define NB   16    // batch rows per persistent CTA
#define NT   512   // threads per CTA

typedef unsigned long long ull;
typedef unsigned uint32;

// ---------------- scratch (static device globals) ----------------
__device__ unsigned   g_sPT[(size_t)Bz * 4096];   // [b][fq*128+lane*4+e] half2(t0,t1) (32 MB)
__device__ ulonglong2 g_HhP[(size_t)Bz * 1024];   // [b][tp*32+lane] fp16 H packed (32 MB)
__device__ float      g_WhT[HZ * 4 * HZ];         // Whh^T [128h][512j]
__device__ ulonglong2 g_fW[14336];                // fp16 ldsm-tiled weights (224 KB)
//  [0,8192) gates (Whh) | [8192,12288) a_next (W1dc) | [12288,14336) W1h (k_init)
__device__ __half     g_hfc[(size_t)Bz * Tz];     // H[b,t]·fcW  (256 KB)

// ---------------- helpers ----------------
__device__ __forceinline__ float wred(float v) {
#pragma unroll
    for (int o = 16; o > 0; o >>= 1) v += __shfl_xor_sync(0xffffffffu, v, o);
    return v;
}
__device__ __forceinline__ float tanh_approx(float x) {
    float r; asm("tanh.approx.f32 %0, %1;" : "=f"(r) : "f"(x)); return r;
}
__device__ __forceinline__ float sigm_t(float x) {          // 1 MUFU sigmoid
    return __fmaf_rn(tanh_approx(0.5f * x), 0.5f, 0.5f);
}
__device__ __forceinline__ __half2 htanh2(__half2 x) {
    unsigned xi = *(unsigned*)&x, r;
    asm("tanh.approx.f16x2 %0, %1;" : "=r"(r) : "r"(xi));
    return *(__half2*)&r;
}
__device__ __forceinline__ ull pack2(float a, float b) {
    return (ull)__float_as_uint(a) | ((ull)__float_as_uint(b) << 32);
}

// ---- tensor-core primitives ----
__device__ __forceinline__ void ldsm4(uint32 &r0, uint32 &r1, uint32 &r2, uint32 &r3, uint32 addr) {
    asm volatile("ldmatrix.sync.aligned.m8n8.x4.shared.b16 {%0,%1,%2,%3}, [%4];"
        : "=r"(r0), "=r"(r1), "=r"(r2), "=r"(r3) : "r"(addr));
}
__device__ __forceinline__ void ldsm4t(uint32 &r0, uint32 &r1, uint32 &r2, uint32 &r3, uint32 addr) {
    asm volatile("ldmatrix.sync.aligned.m8n8.x4.trans.shared.b16 {%0,%1,%2,%3}, [%4];"
        : "=r"(r0), "=r"(r1), "=r"(r2), "=r"(r3) : "r"(addr));
}
__device__ __forceinline__ void mma16816(float4 &d, uint32 a0, uint32 a1, uint32 a2, uint32 a3,
                                         uint32 b0, uint32 b1) {
    asm volatile("mma.sync.aligned.m16n8k16.row.col.f32.f16.f16.f32 "
        "{%0,%1,%2,%3}, {%4,%5,%6,%7}, {%8,%9}, {%0,%1,%2,%3};"
        : "+f"(d.x), "+f"(d.y), "+f"(d.z), "+f"(d.w)
        : "r"(a0), "r"(a1), "r"(a2), "r"(a3), "r"(b0), "r"(b1));
}

// ---------------------------------------------------------------------------
// k_tr: tiled transpose Whh [512,128] -> g_WhT [128,512]
// ---------------------------------------------------------------------------
__global__ void k_tr(const float* __restrict__ Whh) {
    __shared__ float tile[32][33];
    int tx = threadIdx.x, ty = threadIdx.y;
    int x = blockIdx.x * 32 + tx;
    int y = blockIdx.y * 32 + ty;
#pragma unroll
    for (int k = 0; k < 32; k += 8)
        tile[ty + k][tx] = Whh[(y + k) * HZ + x];
    __syncthreads();
    int x2 = blockIdx.y * 32 + tx;
    int y2 = blockIdx.x * 32 + ty;
#pragma unroll
    for (int k = 0; k < 32; k += 8)
        g_WhT[(y2 + k) * 512 + x2] = tile[tx][ty + k];
}

// ---------------------------------------------------------------------------
// k_pack: ldsm-tiled fp16 weights (gates / a_next / W1h-for-init)
// ---------------------------------------------------------------------------
__global__ void k_pack(const float* __restrict__ W1) {
    int idx = blockIdx.x * 256 + threadIdx.x;   // 0..14335
    if (idx >= 14336) return;
    union { ulonglong2 v; __half h[8]; } u;
    if (idx < 8192) {
        int kr = idx & 7, tile = idx >> 3;
        int kt = tile & 15, ng8 = (tile >> 4) & 7, wg = tile >> 7;
        int G = ng8 >> 1, half = ng8 & 1;
        int k = kt * 8 + kr;
        int jb = G * 128 + wg * 16 + half * 8;
#pragma unroll
        for (int nc = 0; nc < 8; ++nc)
            u.h[nc] = __float2half(g_WhT[k * 512 + jb + nc]);
    } else if (idx < 12288) {
        int e = idx - 8192;
        int kr = e & 7, tile = e >> 3;
        int kt = tile & 31, ng = (tile >> 5) & 1, wg = tile >> 6;
        int k = kt * 8 + kr;
        int jb = wg * 16 + ng * 8;
#pragma unroll
        for (int nc = 0; nc < 8; ++nc)
            u.h[nc] = __float2half(__ldg(&W1[k * 128 + jb + nc]));
    } else {
        int e = idx - 12288;
        int kr = e & 7, tile = e >> 3;
        int kt = tile & 15, nt = tile >> 4;
        int k = kt * 8 + kr;
#pragma unroll
        for (int nc = 0; nc < 8; ++nc)
            u.h[nc] = __float2half(__ldg(&W1[(256 + k) * FZ + nt * 8 + nc]));
    }
    g_fW[idx] = u.v;
}

// ---------------------------------------------------------------------------
// k_init (HMMA): sP = H @ W1h + b1 via m16n8k16; also g_HhP + hfc.
// ---------------------------------------------------------------------------
#define KI_SH    0                    // half[64*136]  H fp16        17408
#define KI_SW    17408                // tiled W1h                   32768
#define KI_SOUT  50176                // half[64*136]  sP fp16       17408
#define KI_SB1   67584                // float[128]                    512
#define SMEM_INIT 68096

__global__ void k_init(const float* __restrict__ H,
                       const float* __restrict__ b1,
                       const float* __restrict__ fcW) {
    extern __shared__ char smraw[];
    uint32 smem0 = (uint32)__cvta_generic_to_shared(smraw);
    __half* sH   = (__half*)(smraw + KI_SH);
    __half* sOut = (__half*)(smraw + KI_SOUT);
    float*  sb1  = (float*)(smraw + KI_SB1);
    int b = blockIdx.x, tid = threadIdx.x;
    int w = tid >> 5, lane = tid & 31;

    const float4* Hb4 = (const float4*)(H + (size_t)b * Tz * HZ);
#pragma unroll
    for (int k = 0; k < 8; ++k) {
        int i4 = tid + k * 256;
        int t = i4 >> 5, f = (i4 & 31) * 4;
        float4 v = __ldg(&Hb4[i4]);
        __half2 h0 = __floats2half2_rn(v.x, v.y);
        __half2 h1 = __floats2half2_rn(v.z, v.w);
        *(__half2*)&sH[t * 136 + f]     = h0;
        *(__half2*)&sH[t * 136 + f + 2] = h1;
    }
    for (int i = tid; i < 2048; i += 256)
        ((ulonglong2*)(smraw + KI_SW))[i] = g_fW[12288 + i];
    if (tid < 128) sb1[tid] = __ldg(&b1[tid]);
    __syncthreads();

    {
        int t = tid >> 2, q = tid & 3;
        float acc = 0.0f;
        const __half2* row = (const __half2*)&sH[t * 136 + q * 32];
#pragma unroll
        for (int fp = 0; fp < 16; ++fp) {
            float2 hv = __half22float2(row[fp]);
            int f = q * 32 + 2 * fp;
            acc += hv.x * __ldg(&fcW[f]) + hv.y * __ldg(&fcW[f + 1]);
        }
        acc += __shfl_xor_sync(0xffffffffu, acc, 1, 4);
        acc += __shfl_xor_sync(0xffffffffu, acc, 2, 4);
        if (q == 0) g_hfc[(size_t)b * Tz + t] = __float2half(acc);
    }

    {
        int mt = w & 3, nh = w >> 2;
        int g = lane >> 2, tig = lane & 3;
        int arow = lane & 15;
        int acol = ((lane >> 4) & 1) * 8;
        uint32 A[8][4];
#pragma unroll
        for (int kt = 0; kt < 8; ++kt)
            ldsm4(A[kt][0], A[kt][1], A[kt][2], A[kt][3],
                  smem0 + KI_SH + (mt * 16 + arow) * 272 + (kt * 16 + acol) * 2);
#pragma unroll
        for (int nt2 = 0; nt2 < 8; ++nt2) {
            int nt = nh * 8 + nt2;
            float4 D = make_float4(0.f, 0.f, 0.f, 0.f);
            uint32 tb = smem0 + KI_SW + nt * 2048 + (lane >> 3) * 128 + (lane & 7) * 16;
#pragma unroll
            for (int kq = 0; kq < 4; ++kq) {
                uint32 b0r, b1r, b2r, b3r;
                ldsm4t(b0r, b1r, b2r, b3r, tb + kq * 512);
                mma16816(D, A[2*kq][0],   A[2*kq][1],   A[2*kq][2],   A[2*kq][3],   b0r, b1r);
                mma16816(D, A[2*kq+1][0], A[2*kq+1][1], A[2*kq+1][2], A[2*kq+1][3], b2r, b3r);
            }
            int f0 = nt * 8 + tig * 2;
            int r0 = mt * 16 + g;
            sOut[r0 * 136 + f0]           = __float2half(D.x + sb1[f0]);
            sOut[r0 * 136 + f0 + 1]       = __float2half(D.y + sb1[f0 + 1]);
            sOut[(r0 + 8) * 136 + f0]     = __float2half(D.z + sb1[f0]);
            sOut[(r0 + 8) * 136 + f0 + 1] = __float2half(D.w + sb1[f0 + 1]);
        }
    }
    __syncthreads();

    unsigned* dst = g_sPT + (size_t)b * 4096;
    for (int i = tid; i < 4096; i += 256) {
        int e = i & 3, ln = (i >> 2) & 31, fq = i >> 7;
        int f = 4 * fq + e;
        __half2 hv = __halves2half2(sOut[(2 * ln) * 136 + f], sOut[(2 * ln + 1) * 136 + f]);
        dst[i] = *(unsigned*)&hv;
    }
    ulonglong2* hdst = g_HhP + (size_t)b * 1024;
    for (int i = tid; i < 1024; i += 256) {
        int tp = i >> 5, ln = i & 31;
        ull ux = *(const ull*)&sH[(2 * tp) * 136 + 4 * ln];
        ull uy = *(const ull*)&sH[(2 * tp + 1) * 136 + 4 * ln];
        hdst[i] = make_ulonglong2(ux, uy);
    }
}

// ---------------------------------------------------------------------------
// k_main: per-step phases:
//   P0: [a_next(t-1) MMA (t>0)] + [gates(t) MMA, D -> smem stash]  -> bar
//   P1: attention(t)                                               -> bar
//   P2: pointwise (D from stash)                                   -> bar
// Gates weights in register fragments; D stashed to smem to free regs in P1.
// ---------------------------------------------------------------------------
#define SM_ANX   0                 // a_next tiles                       65536
#define SM_DST   65536             // D stash float4[4][512]             32768
#define SM_SAH   98304             // half[16*128] a                      4096
#define SM_SDH0  102400            // half d buf0 [16 x RB_H]             4352
#define SM_SDH1  106752            // half d buf1                         4352
#define SM_SCH   111104            // half c (a_next A operand)           4352
#define SM_SCF   115456            // float c-state [16 x RB_F]           8448
#define SM_HFC   123904            // half[16*64]                         2048
#define SM_W2    125952            // float[128]                           512
#define SM_WIH   126464            // float[512]                          2048
#define SM_BIA   128512            // float[512]                          2048
#define SM_SY    130560            // float[16]
#define SM_CTXD  130624            // float[16]
#define SMEM_MAIN 130688

#define RB_H 136
#define RB_F 132

__device__ __forceinline__ void attn_row(
    int row, int b, int t, int lane, bool do_ctx,
    const __half* sah, const float* sw2, const __half2* shfc2,
    float* sy, float* sctxd,
    const float* __restrict__ Y, float fwy, float fb0,
    const float* __restrict__ fcfW)
{
    const uint4* pT4 = (const uint4*)(g_sPT + (size_t)b * 4096);
    const ull* sar4 = (const ull*)(sah + row * HZ);
    float s0 = 0.0f, s1 = 0.0f;
#pragma unroll 8
    for (int fq = 0; fq < 32; ++fq) {
        uint4 pv = pT4[fq * 32 + lane];
        ull av = sar4[fq];
        float4 wf = *(const float4*)&sw2[4 * fq];
        __half ah[4]; *(ull*)ah = av;
        __half2 t0 = htanh2(__hadd2(*(__half2*)&pv.x, __half2half2(ah[0])));
        __half2 t1 = htanh2(__hadd2(*(__half2*)&pv.y, __half2half2(ah[1])));
        __half2 t2 = htanh2(__hadd2(*(__half2*)&pv.z, __half2half2(ah[2])));
        __half2 t3 = htanh2(__hadd2(*(__half2*)&pv.w, __half2half2(ah[3])));
        float2 f0 = __half22float2(t0), f1 = __half22float2(t1);
        float2 f2 = __half22float2(t2), f3 = __half22float2(t3);
        s0 += f0.x * wf.x + f1.x * wf.y + f2.x * wf.z + f3.x * wf.w;
        s1 += f0.y * wf.x + f1.y * wf.y + f2.y * wf.z + f3.y * wf.w;
    }
    float m = fmaxf(s0, s1);
#pragma unroll
    for (int o = 16; o > 0; o >>= 1) m = fmaxf(m, __shfl_xor_sync(0xffffffffu, m, o));
    float e0 = __expf(s0 - m), e1 = __expf(s1 - m);
    float ssum = wred(e0 + e1);
    float inv = __fdividef(1.0f, ssum);
    float beta0 = e0 * inv, beta1 = e1 * inv;

    float2 hc = __half22float2(shfc2[row * 32 + lane]);
    float part = beta0 * hc.x + beta1 * hc.y;
    part = wred(part);
    if (lane == 0)
        sy[row] = part + __ldg(&Y[b * Tz + t]) * fwy + fb0;

    if (do_ctx) {
        const ulonglong2* HbP = g_HhP + (size_t)b * 1024;
        float c0 = 0.f, c1 = 0.f, c2 = 0.f, c3 = 0.f;
#pragma unroll 4
        for (int tp = 0; tp < 32; ++tp) {
            float bbA = __shfl_sync(0xffffffffu, beta0, tp);
            float bbB = __shfl_sync(0xffffffffu, beta1, tp);
            ulonglong2 hv = __ldcs(&HbP[tp * 32 + lane]);
            __half2* hh = (__half2*)&hv;
            float2 a0 = __half22float2(hh[0]), a1 = __half22float2(hh[1]);
            float2 g0 = __half22float2(hh[2]), g1 = __half22float2(hh[3]);
            c0 += bbA * a0.x + bbB * g0.x;
            c1 += bbA * a0.y + bbB * g0.y;
            c2 += bbA * a1.x + bbB * g1.x;
            c3 += bbA * a1.y + bbB * g1.y;
        }
        float4 f2 = *(const float4*)&fcfW[128 + 4 * lane];
        float cd = c0 * f2.x + c1 * f2.y + c2 * f2.z + c3 * f2.w;
        cd = wred(cd);
        if (lane == 0) sctxd[row] = cd;
    }
}

__global__ void __launch_bounds__(NT, 1)
k_main(const float* __restrict__ Y,
       const float* __restrict__ W2,
       const float* __restrict__ W_ih,
       const float* __restrict__ b_ih,
       const float* __restrict__ b_hh,
       const float* __restrict__ fcW,
       const float* __restrict__ fcb,
       const float* __restrict__ fcfW,
       const float* __restrict__ fcfb,
       float* __restrict__ out) {
    extern __shared__ char smraw[];
    uint32 smem0 = (uint32)__cvta_generic_to_shared(smraw);
    float4*  dstash = (float4*)(smraw + SM_DST);
    __half*  sah   = (__half*)(smraw + SM_SAH);
    __half*  sch   = (__half*)(smraw + SM_SCH);
    float*   scf   = (float*)(smraw + SM_SCF);
    __half2* shfc2 = (__half2*)(smraw + SM_HFC);
    float*   sw2   = (float*)(smraw + SM_W2);
    float*   swih  = (float*)(smraw + SM_WIH);
    float*   sbia  = (float*)(smraw + SM_BIA);
    float*   sy    = (float*)(smraw + SM_SY);
    float*   sctxd = (float*)(smraw + SM_CTXD);

    int tid = threadIdx.x, w = tid >> 5, lane = tid & 31;
    int b0 = blockIdx.x * NB;
    int g = lane >> 2, tig = lane & 3;
    int wg2 = w;

    // ---- stage gates weights -> register fragments (2 chunks of 64 KB) ----
    uint32 BG[64];
    {
        int lanehi = (lane >> 3) * 128 + (lane & 7) * 16;
        for (int i = tid; i < 4096; i += NT)
            ((ulonglong2*)smraw)[i] = g_fW[i];
        __syncthreads();
        if (wg2 < 8) {
#pragma unroll
            for (int G = 0; G < 4; ++G) {
                int grp = (wg2 >> 1) * 8 + G * 2 + (wg2 & 1);
                uint32 tb = smem0 + grp * 2048 + lanehi;
#pragma unroll
                for (int kq = 0; kq < 4; ++kq)
                    ldsm4t(BG[G*16 + kq*4 + 0], BG[G*16 + kq*4 + 1],
                           BG[G*16 + kq*4 + 2], BG[G*16 + kq*4 + 3], tb + kq * 512);
            }
        }
        __syncthreads();
        for (int i = tid; i < 4096; i += NT)
            ((ulonglong2*)smraw)[i] = g_fW[4096 + i];
        __syncthreads();
        if (wg2 >= 8) {
#pragma unroll
            for (int G = 0; G < 4; ++G) {
                int grp = (wg2 >> 1) * 8 + G * 2 + (wg2 & 1) - 32;
                uint32 tb = smem0 + grp * 2048 + lanehi;
#pragma unroll
                for (int kq = 0; kq < 4; ++kq)
                    ldsm4t(BG[G*16 + kq*4 + 0], BG[G*16 + kq*4 + 1],
                           BG[G*16 + kq*4 + 2], BG[G*16 + kq*4 + 3], tb + kq * 512);
            }
        }
        __syncthreads();
        for (int i = tid; i < 4096; i += NT)
            ((ulonglong2*)smraw)[i] = g_fW[8192 + i];
    }

    for (int i = tid; i < NB * HZ; i += NT)
        sah[i] = __float2half(0.0f);
    {
        __half z = __float2half(0.0f);
        __half* sdh0 = (__half*)(smraw + SM_SDH0);
        __half* sdh1 = (__half*)(smraw + SM_SDH1);
        for (int i = tid; i < NB * RB_H; i += NT) { sdh0[i] = z; sdh1[i] = z; sch[i] = z; }
        for (int i = tid; i < NB * RB_F; i += NT) scf[i] = 0.0f;
    }
    for (int i = tid; i < NB * Tz / 2; i += NT)
        shfc2[i] = ((const __half2*)g_hfc)[b0 * 32 + i];
    if (tid < FZ) sw2[tid] = __ldg(&W2[tid]);
    for (int i = tid; i < 512; i += NT) {
        swih[i] = __ldg(&W_ih[i]);
        sbia[i] = __ldg(&b_ih[i]) + __ldg(&b_hh[i]);
    }

    float fwy = __ldg(&fcW[HZ]), fb0 = __ldg(&fcb[0]);
    __syncthreads();

    uint32 abase = smem0 + SM_ANX + wg2 * 4096 + (lane >> 3) * 128 + (lane & 7) * 16;
    int jjb = wg2 * 8 + tig * 2;
    int arow = (lane & 7) + (lane & 8);
    int acol = ((lane >> 4) & 1) * 8;

    for (int t = 0; t < Tz; ++t) {
        uint32 sdhP = smem0 + ((t & 1) ? SM_SDH1 : SM_SDH0);
        __half* sdhNg = (__half*)(smraw + ((t & 1) ? SM_SDH0 : SM_SDH1));

        // ============ P0: a_next(t-1) + gates(t) MMA ======================
        if (t > 0) {
            // a_next(t-1): A = [d(t-1) | c(t-1)] (sdhP / sch), writes sah
            uint32 schU = smem0 + SM_SCH;
            float4 Da = make_float4(0.f, 0.f, 0.f, 0.f);
#pragma unroll
            for (int kq = 0; kq < 8; ++kq) {
                uint32 b0r, b1r, b2r, b3r;
                ldsm4t(b0r, b1r, b2r, b3r, abase + kq * 512);
                int m0 = 2 * kq, m1 = 2 * kq + 1;
                uint32 a0, a1, a2, a3;
                {
                    uint32 base = (m0 < 8) ? sdhP : schU;
                    int kc = (m0 & 7) * 16;
                    ldsm4(a0, a1, a2, a3, base + arow * (RB_H * 2) + (kc + acol) * 2);
                    mma16816(Da, a0, a1, a2, a3, b0r, b1r);
                }
                {
                    uint32 base = (m1 < 8) ? sdhP : schU;
                    int kc = (m1 & 7) * 16;
                    ldsm4(a0, a1, a2, a3, base + arow * (RB_H * 2) + (kc + acol) * 2);
                    mma16816(Da, a0, a1, a2, a3, b2r, b3r);
                }
            }
            sah[g * HZ + jjb]           = __float2half(Da.x);
            sah[g * HZ + jjb + 1]       = __float2half(Da.y);
            sah[(g + 8) * HZ + jjb]     = __float2half(Da.z);
            sah[(g + 8) * HZ + jjb + 1] = __float2half(Da.w);
        }
        {
            // gates(t): A = d(t-1), B = register frags; D -> smem stash
            uint32 A[8][4];
#pragma unroll
            for (int kt = 0; kt < 8; ++kt)
                ldsm4(A[kt][0], A[kt][1], A[kt][2], A[kt][3],
                      sdhP + arow * (RB_H * 2) + (kt * 16 + acol) * 2);
#pragma unroll
            for (int G = 0; G < 4; ++G) {
                float4 D = make_float4(0.f, 0.f, 0.f, 0.f);
#pragma unroll
                for (int kq = 0; kq < 4; ++kq) {
                    mma16816(D, A[2*kq][0],   A[2*kq][1],   A[2*kq][2],   A[2*kq][3],
                             BG[G*16 + kq*4 + 0], BG[G*16 + kq*4 + 1]);
                    mma16816(D, A[2*kq+1][0], A[2*kq+1][1], A[2*kq+1][2], A[2*kq+1][3],
                             BG[G*16 + kq*4 + 2], BG[G*16 + kq*4 + 3]);
                }
                dstash[G * NT + tid] = D;
            }
        }
        __syncthreads();

        // ============ P1: attention (D not live; regs free for MLP) =======
        attn_row(w, b0 + w, t, lane, t == Tz - 1,
                 sah, sw2, shfc2, sy, sctxd, Y, fwy, fb0, fcfW);
        __syncthreads();

        // ============ P2: pointwise (reload D from stash) =================
        {
            float4 D0 = dstash[0 * NT + tid];
            float4 D1 = dstash[1 * NT + tid];
            float4 D2 = dstash[2 * NT + tid];
            float4 D3 = dstash[3 * NT + tid];
            float yt0 = sy[g], yt1 = sy[g + 8];
#pragma unroll
            for (int e = 0; e < 2; ++e) {
                int jj = jjb + e;
                float wi0 = swih[jj],      bi0 = sbia[jj];
                float wi1 = swih[jj+128],  bi1 = sbia[jj+128];
                float wi2 = swih[jj+256],  bi2 = sbia[jj+256];
                float wi3 = swih[jj+384],  bi3 = sbia[jj+384];
#pragma unroll
                for (int rr = 0; rr < 2; ++rr) {
                    int row = g + rr * 8;
                    float yt = rr ? yt1 : yt0;
                    float gi = (e ? (rr ? D0.w : D0.y) : (rr ? D0.z : D0.x)) + yt * wi0 + bi0;
                    float gf = (e ? (rr ? D1.w : D1.y) : (rr ? D1.z : D1.x)) + yt * wi1 + bi1;
                    float gg = (e ? (rr ? D2.w : D2.y) : (rr ? D2.z : D2.x)) + yt * wi2 + bi2;
                    float go = (e ? (rr ? D3.w : D3.y) : (rr ? D3.z : D3.x)) + yt * wi3 + bi3;
                    float cold = scf[row * RB_F + jj];
                    float cn = sigm_t(gf) * cold + sigm_t(gi) * tanh_approx(gg);
                    float dn = sigm_t(go) * tanh_approx(cn);
                    scf[row * RB_F + jj] = cn;
                    sdhNg[row * RB_H + jj] = __float2half(dn);
                    sch[row * RB_H + jj]   = __float2half(cn);
                }
            }
        }
        __syncthreads();
    }

    // ---- final: out[b] = d·fcf[0:128] + ctxd + fcfb ----
    {
        const __half* sdh0 = (const __half*)(smraw + SM_SDH0);
        int row = w;
        float4 fa = *(const float4*)&fcfW[4 * lane];
        ull hv = *(const ull*)&sdh0[row * RB_H + 4 * lane];
        __half2* hh = (__half2*)&hv;
        float2 d01 = __half22float2(hh[0]), d23 = __half22float2(hh[1]);
        float s = d01.x * fa.x + d01.y * fa.y + d23.x * fa.z + d23.y * fa.w;
        s = wred(s);
        if (lane == 0) out[b0 + row] = s + sctxd[row] + __ldg(&fcfb[0]);
    }
}

extern "C" void kernel_launch(void* const* d_in, const int* in_sizes, int n_in,
                              void* d_out, int out_size) {
    (void)in_sizes; (void)n_in; (void)out_size;
    const float* H    = (const float*)d_in[0];
    const float* Y    = (const float*)d_in[1];
    const float* W1   = (const float*)d_in[2];
    const float* b1   = (const float*)d_in[3];
    const float* W2   = (const float*)d_in[4];
    // d_in[5] = attn_b2: cancels in softmax.
    const float* W_ih = (const float*)d_in[6];
    const float* Whh  = (const float*)d_in[7];
    const float* b_ih = (const float*)d_in[8];
    const float* b_hh = (const float*)d_in[9];
    const float* fcW  = (const float*)d_in[10];
    const float* fcb  = (const float*)d_in[11];
    const float* fcfW = (const float*)d_in[12];
    const float* fcfb = (const float*)d_in[13];
    float* out = (float*)d_out;

    static int configured = 0;
    if (!configured) {
        cudaFuncSetAttribute(k_init, cudaFuncAttributeMaxDynamicSharedMemorySize, SMEM_INIT);
        cudaFuncSetAttribute(k_main, cudaFuncAttributeMaxDynamicSharedMemorySize, SMEM_MAIN);
        configured = 1;
    }

    k_tr<<<dim3(4, 16), dim3(32, 8)>>>(Whh);
    k_pack<<<56, 256>>>(W1);
    k_init<<<Bz, 256, SMEM_INIT>>>(H, b1, fcW);
    k_main<<<Bz / NB, NT, SMEM_MAIN>>>(Y, W2, W_ih, b_ih, b_hh, fcW, fcb, fcfW, fcfb, out);
}